// round 7
// baseline (speedup 1.0000x reference)
#include <cuda_runtime.h>
#include <cuda_bf16.h>
#include <cstdint>

#define BB 128
#define TT 256
#define DD 64
#define HH 512
#define NBLK 128
#define NTHR 512
#define PRED_SZ (BB*(TT-1)*DD)

// smem byte layout
#define SM_A0HI 0
#define SM_A0LO 16384
#define SM_A1HI 32768
#define SM_A1LO 49152
#define W1_STRIDE 584                       // 576 k + 8 pad (elems)
#define W2_STRIDE 1032                      // 1024 k + 8 pad
#define SM_W1HI 65536
#define SM_W1LO (SM_W1HI + 16*W1_STRIDE*2)  // 84224
#define SM_W2HI (SM_W1LO + 16*W1_STRIDE*2)  // 102912
#define SM_W2LO (SM_W2HI + 16*W2_STRIDE*2)  // 135936
#define SM_WP   (SM_W2LO + 16*W2_STRIDE*2)  // 168960
#define SM_TOTAL (SM_WP + 2048)             // 171008

__device__ float g_h1[2][BB*HH];
__device__ float g_h2[2][BB*HH];
__device__ float g_cur[BB*DD];
__device__ unsigned int g_bar;

__device__ __forceinline__ uint32_t smem_u32(const void* p) {
    uint32_t a;
    asm("{ .reg .u64 t; cvta.to.shared.u64 t, %1; cvt.u32.u64 %0, t; }" : "=r"(a) : "l"(p));
    return a;
}
__device__ __forceinline__ uint32_t cvt2(float lo, float hi) {
    uint32_t r; asm("cvt.rn.satfinite.bf16x2.f32 %0, %1, %2;" : "=r"(r) : "f"(hi), "f"(lo)); return r;
}
__device__ __forceinline__ void ldsm4(uint32_t r[4], uint32_t addr) {
    asm volatile("ldmatrix.sync.aligned.m8n8.x4.shared.b16 {%0,%1,%2,%3}, [%4];"
        : "=r"(r[0]), "=r"(r[1]), "=r"(r[2]), "=r"(r[3]) : "r"(addr));
}
__device__ __forceinline__ void mma_bf16(float c[4], const uint32_t a[4], uint32_t b0, uint32_t b1) {
    asm volatile("mma.sync.aligned.m16n8k16.row.col.f32.bf16.bf16.f32 "
        "{%0,%1,%2,%3}, {%4,%5,%6,%7}, {%8,%9}, {%0,%1,%2,%3};"
        : "+f"(c[0]), "+f"(c[1]), "+f"(c[2]), "+f"(c[3])
        : "r"(a[0]), "r"(a[1]), "r"(a[2]), "r"(a[3]), "r"(b0), "r"(b1));
}

__device__ __forceinline__ void grid_barrier() {
    __syncthreads();
    if (threadIdx.x == 0) {
        __threadfence();
        unsigned my = atomicAdd(&g_bar, 1u) + 1u;
        unsigned target = my + (NBLK - 1u) - ((my - 1u) % NBLK);
        while ((int)(*(volatile unsigned*)&g_bar - target) < 0) __nanosleep(32);
        __threadfence();
    }
    __syncthreads();
}

// ---- producer: split LDG (to regs) and CVT+STS (regs -> swizzled bf16 tiles) ----
__device__ __forceinline__ void ldg_chunk(float4 pf[8], const float* __restrict__ src,
                                          int stride, int stid) {
    #pragma unroll
    for (int q = 0; q < 8; q++) {
        int lin = q*256 + stid;
        int r = lin >> 4, f4 = lin & 15;
        pf[q] = *(const float4*)(src + r*stride + f4*4);
    }
}
__device__ __forceinline__ void cvt_sts(char* bhi, char* blo, const float4 pf[8], int stid) {
    #pragma unroll
    for (int q = 0; q < 8; q++) {
        int lin = q*256 + stid;
        int r = lin >> 4, f4 = lin & 15;
        float4 v = pf[q];
        uint32_t h01 = cvt2(v.x, v.y);
        uint32_t h23 = cvt2(v.z, v.w);
        float bx = __uint_as_float(h01 << 16), by = __uint_as_float(h01 & 0xffff0000u);
        float bz = __uint_as_float(h23 << 16), bw = __uint_as_float(h23 & 0xffff0000u);
        uint32_t l01 = cvt2(v.x - bx, v.y - by);
        uint32_t l23 = cvt2(v.z - bz, v.w - bw);
        int u = f4 >> 1;
        uint32_t off = (uint32_t)(r*128 + ((u ^ (r & 7)) << 4) + (f4 & 1)*8);
        *(uint2*)(bhi + off) = make_uint2(h01, h23);
        *(uint2*)(blo + off) = make_uint2(l01, l23);
    }
}

// One 64-k chunk of MMAs. bhi/blo already offset to chunk (= base + lane_off + c*128).
__device__ __forceinline__ void mma_chunk(float C0[4], float C1[4],
    uint32_t a_hi, uint32_t a_lo, int rsw, int ahalf, uint32_t bhi, uint32_t blo) {
    #pragma unroll
    for (int kk = 0; kk < 4; kk++) {
        uint32_t asw = (uint32_t)(((2*kk + ahalf) ^ rsw) << 4);
        uint32_t ah[4], al[4], bh[4], bl[4];
        ldsm4(ah, a_hi + asw);
        ldsm4(al, a_lo + asw);
        ldsm4(bh, bhi + kk*32);
        ldsm4(bl, blo + kk*32);
        mma_bf16(C0, ah, bh[0], bh[1]);
        mma_bf16(C1, ah, bh[2], bh[3]);
        mma_bf16(C0, ah, bl[0], bl[1]);
        mma_bf16(C1, ah, bl[2], bl[3]);
        mma_bf16(C0, al, bh[0], bh[1]);
        mma_bf16(C1, al, bh[2], bh[3]);
    }
}

__device__ __forceinline__ void gates2(const float C0[4], const float C1[4],
    float bi, float bf_, float bg, float bo, float cst[2], float hout[2]) {
    #pragma unroll
    for (int h = 0; h < 2; h++) {
        float zi = C0[2*h] + bi, zf = C0[2*h+1] + bf_;
        float zg = C1[2*h] + bg, zo = C1[2*h+1] + bo;
        float ig = 1.f/(1.f + expf(-zi));
        float fg = 1.f/(1.f + expf(-zf));
        float gg = tanhf(zg);
        float og = 1.f/(1.f + expf(-zo));
        float cn = fg*cst[h] + ig*gg;
        cst[h] = cn;
        hout[h] = og*tanhf(cn);
    }
}

__global__ void __launch_bounds__(NTHR, 1) ajrnn_kernel(
    const float* __restrict__ x,
    const float* __restrict__ k0, const float* __restrict__ r0, const float* __restrict__ b0,
    const float* __restrict__ k1, const float* __restrict__ r1, const float* __restrict__ b1,
    const float* __restrict__ Wm, const float* __restrict__ bias,
    float* __restrict__ out)
{
    extern __shared__ char smem[];
    const uint32_t smb = smem_u32(smem);
    const int tid = threadIdx.x;
    const int bid = blockIdx.x;
    const int n0  = bid * 4;
    const int dcol = bid >> 1;
    const int wid = tid >> 5, lane = tid & 31;
    float* sh_wp = (float*)(smem + SM_WP);

    // ---- weights: fp32 -> bf16 hi/lo, gate-interleaved col order ----
    unsigned short* w1h = (unsigned short*)(smem + SM_W1HI);
    unsigned short* w1l = (unsigned short*)(smem + SM_W1LO);
    unsigned short* w2h = (unsigned short*)(smem + SM_W2HI);
    unsigned short* w2l = (unsigned short*)(smem + SM_W2LO);
    for (int idx = tid; idx < 16*576; idx += NTHR) {
        int p = idx & 15, k = idx >> 4;
        int col = (2*(p>>3) + (p&1))*HH + n0 + ((p&7)>>1);
        float w = (k < DD) ? k0[k*2048 + col] : r0[(k-DD)*2048 + col];
        __nv_bfloat16 hb = __float2bfloat16(w);
        __nv_bfloat16 lb = __float2bfloat16(w - __bfloat162float(hb));
        w1h[p*W1_STRIDE + k] = __bfloat16_as_ushort(hb);
        w1l[p*W1_STRIDE + k] = __bfloat16_as_ushort(lb);
    }
    for (int idx = tid; idx < 16*1024; idx += NTHR) {
        int p = idx & 15, k = idx >> 4;
        int col = (2*(p>>3) + (p&1))*HH + n0 + ((p&7)>>1);
        float w = (k < HH) ? k1[k*2048 + col] : r1[(k-HH)*2048 + col];
        __nv_bfloat16 hb = __float2bfloat16(w);
        __nv_bfloat16 lb = __float2bfloat16(w - __bfloat162float(hb));
        w2h[p*W2_STRIDE + k] = __bfloat16_as_ushort(hb);
        w2l[p*W2_STRIDE + k] = __bfloat16_as_ushort(lb);
    }
    sh_wp[tid] = Wm[tid*DD + dcol];
    g_h1[0][bid*HH + tid] = 0.f;
    g_h2[0][bid*HH + tid] = 0.f;
    const float biasd = bias[dcol];

    const int jj = lane & 3;
    const float bi0 = b0[0*HH + n0 + jj], bf0 = b0[1*HH + n0 + jj];
    const float bg0 = b0[2*HH + n0 + jj], bo0 = b0[3*HH + n0 + jj];
    const float bi1 = b1[0*HH + n0 + jj], bf1 = b1[1*HH + n0 + jj];
    const float bg1 = b1[2*HH + n0 + jj], bo1 = b1[3*HH + n0 + jj];

    const int arow  = ((wid & 7) << 4) + (lane & 15);
    const int rsw   = arow & 7;
    const int ahalf = lane >> 4;
    const uint32_t a_row_off = (uint32_t)(arow * 128);
    const int bn  = (lane & 7) | ((lane >> 1) & 8);
    const int bk8 = (lane >> 3) & 1;
    const uint32_t b1h = smb + SM_W1HI + bn*(W1_STRIDE*2) + bk8*16;
    const uint32_t b1lo = smb + SM_W1LO + bn*(W1_STRIDE*2) + bk8*16;
    const uint32_t b2h = smb + SM_W2HI + bn*(W2_STRIDE*2) + bk8*16;
    const uint32_t b2lo = smb + SM_W2LO + bn*(W2_STRIDE*2) + bk8*16;
    const int crow = ((wid & 7) << 4) + (lane >> 2);
    const bool producer = (wid >= 8);
    const int stid = tid & 255;

    char* const bufhi0 = smem + SM_A0HI;
    char* const buflo0 = smem + SM_A0LO;
    char* const bufhi1 = smem + SM_A1HI;
    char* const buflo1 = smem + SM_A1LO;

    float c1st[2] = {0.f, 0.f}, c2st[2] = {0.f, 0.f};
    grid_barrier();

    // ---------------- time loop ----------------
    for (int t = 0; t < TT; t++) {
        const int rb = t & 1;
        const int wb = rb ^ 1;

        // ---- Phase A: pred (-> out) + imputed cur ----
        {
            const int r  = ((bid & 1) * 64) + (tid >> 3);
            const int l8 = tid & 7;
            if (t == 0) {
                if (l8 == 0) g_cur[r*DD + dcol] = x[(r*TT)*DD + dcol];
            } else {
                const float* hrow = &g_h2[rb][r*HH + l8*64];
                const float* wv = sh_wp + l8*64;
                float sacc = 0.f;
                #pragma unroll
                for (int kk = 0; kk < 64; kk += 4) {
                    float4 h4 = *(const float4*)(hrow + kk);
                    sacc += h4.x*wv[kk] + h4.y*wv[kk+1] + h4.z*wv[kk+2] + h4.w*wv[kk+3];
                }
                sacc += __shfl_xor_sync(0xffffffffu, sacc, 4);
                sacc += __shfl_xor_sync(0xffffffffu, sacc, 2);
                sacc += __shfl_xor_sync(0xffffffffu, sacc, 1);
                if (l8 == 0) {
                    float p  = sacc + biasd;
                    float xv = x[(r*TT + t)*DD + dcol];
                    g_cur[r*DD + dcol] = (xv == 128.0f) ? p : xv;
                    out[(r*(TT-1) + (t-1))*DD + dcol] = p;
                }
            }
        }
        grid_barrier();

        // ---- Phase B: z = [cur | h1_old] @ W1, 9 chunks, 2-deep LDG pipeline ----
        {
            float C0[4] = {0,0,0,0}, C1[4] = {0,0,0,0};
            float4 pfA[8], pfB[8];                 // pfA: even chunks, pfB: odd chunks
            if (producer) {
                ldg_chunk(pfA, g_cur, DD, stid);   // chunk 0
                cvt_sts(bufhi0, buflo0, pfA, stid);
                ldg_chunk(pfB, g_h1[rb], HH, stid); // chunk 1
            }
            __syncthreads();
            #pragma unroll 1
            for (int c = 0; c < 9; c++) {
                if (producer) {
                    // STS chunk c+1 (loaded last iter), LDG chunk c+2
                    if ((c & 1) == 0) {
                        if (c + 1 < 9) cvt_sts(bufhi1, buflo1, pfB, stid);
                        if (c + 2 < 9) ldg_chunk(pfA, g_h1[rb] + (c+1)*64, HH, stid);
                    } else {
                        if (c + 1 < 9) cvt_sts(bufhi0, buflo0, pfA, stid);
                        if (c + 2 < 9) ldg_chunk(pfB, g_h1[rb] + (c+1)*64, HH, stid);
                    }
                } else {
                    uint32_t ah = smb + ((c&1) ? SM_A1HI : SM_A0HI) + a_row_off;
                    uint32_t al = smb + ((c&1) ? SM_A1LO : SM_A0LO) + a_row_off;
                    mma_chunk(C0, C1, ah, al, rsw, ahalf, b1h + c*128, b1lo + c*128);
                }
                __syncthreads();
            }
            if (!producer) {
                float hout[2];
                gates2(C0, C1, bi0, bf0, bg0, bo0, c1st, hout);
                g_h1[wb][crow*HH + n0 + jj]     = hout[0];
                g_h1[wb][(crow+8)*HH + n0 + jj] = hout[1];
            }
        }
        grid_barrier();

        // ---- Phase C: z = [h1_new | h2_old] @ W2, 16 chunks, 2-deep LDG pipeline ----
        {
            float C0[4] = {0,0,0,0}, C1[4] = {0,0,0,0};
            float4 pfA[8], pfB[8];
            if (producer) {
                ldg_chunk(pfA, g_h1[wb], HH, stid);       // chunk 0
                cvt_sts(bufhi0, buflo0, pfA, stid);
                ldg_chunk(pfB, g_h1[wb] + 64, HH, stid);  // chunk 1
            }
            __syncthreads();
            #pragma unroll 1
            for (int c = 0; c < 16; c++) {
                if (producer) {
                    if (c + 2 < 16) {
                        int cc = c + 2;
                        const float* src = (cc < 8) ? (g_h1[wb] + cc*64) : (g_h2[rb] + (cc-8)*64);
                        if ((c & 1) == 0) {
                            cvt_sts(bufhi1, buflo1, pfB, stid);
                            ldg_chunk(pfA, src, HH, stid);
                        } else {
                            cvt_sts(bufhi0, buflo0, pfA, stid);
                            ldg_chunk(pfB, src, HH, stid);
                        }
                    } else if (c + 1 < 16) {
                        if ((c & 1) == 0) cvt_sts(bufhi1, buflo1, pfB, stid);
                        else              cvt_sts(bufhi0, buflo0, pfA, stid);
                    }
                } else {
                    uint32_t ah = smb + ((c&1) ? SM_A1HI : SM_A0HI) + a_row_off;
                    uint32_t al = smb + ((c&1) ? SM_A1LO : SM_A0LO) + a_row_off;
                    mma_chunk(C0, C1, ah, al, rsw, ahalf, b2h + c*128, b2lo + c*128);
                }
                __syncthreads();
            }
            if (!producer) {
                float hout[2];
                gates2(C0, C1, bi1, bf1, bg1, bo1, c2st, hout);
                g_h2[wb][crow*HH + n0 + jj]     = hout[0];
                g_h2[wb][(crow+8)*HH + n0 + jj] = hout[1];
                if (t == TT-1) {
                    out[PRED_SZ + crow*HH + n0 + jj]     = hout[0];
                    out[PRED_SZ + (crow+8)*HH + n0 + jj] = hout[1];
                }
            }
        }
        grid_barrier();
    }
}

extern "C" void kernel_launch(void* const* d_in, const int* in_sizes, int n_in,
                              void* d_out, int out_size) {
    (void)in_sizes; (void)n_in; (void)out_size;
    const float* x    = (const float*)d_in[0];
    const float* k0   = (const float*)d_in[1];
    const float* r0   = (const float*)d_in[2];
    const float* b0   = (const float*)d_in[3];
    const float* k1   = (const float*)d_in[4];
    const float* r1   = (const float*)d_in[5];
    const float* b1   = (const float*)d_in[6];
    const float* Wm   = (const float*)d_in[7];
    const float* bias = (const float*)d_in[8];
    cudaFuncSetAttribute(ajrnn_kernel, cudaFuncAttributeMaxDynamicSharedMemorySize, SM_TOTAL);
    ajrnn_kernel<<<NBLK, NTHR, SM_TOTAL>>>(x, k0, r0, b0, k1, r1, b1, Wm, bias, (float*)d_out);
}

// round 8
// speedup vs baseline: 1.4222x; 1.4222x over previous
#include <cuda_runtime.h>
#include <cuda_bf16.h>
#include <cstdint>

#define BB 128
#define TT 256
#define DD 64
#define HH 512
#define NBLK 128
#define NTHR 512
#define PRED_SZ (BB*(TT-1)*DD)

// smem byte layout
#define SM_A0HI 0
#define SM_A0LO 16384
#define SM_A1HI 32768
#define SM_A1LO 49152
#define W1_STRIDE 584
#define W2_STRIDE 1032
#define SM_W1HI 65536
#define SM_W1LO (SM_W1HI + 16*W1_STRIDE*2)
#define SM_W2HI (SM_W1LO + 16*W1_STRIDE*2)
#define SM_W2LO (SM_W2HI + 16*W2_STRIDE*2)
#define SM_WP   (SM_W2LO + 16*W2_STRIDE*2)
#define SM_TOTAL (SM_WP + 2048)

// h state kept as PRE-SWIZZLED bf16 hi/lo arrays (ldmatrix tile byte layout),
// plus an fp32 copy of h2 for the pred FFMA phase.
__device__ __align__(16) unsigned short g_h1h[2][BB*HH], g_h1l[2][BB*HH];
__device__ __align__(16) unsigned short g_h2h[2][BB*HH], g_h2l[2][BB*HH];
__device__ __align__(16) float g_h2f[2][BB*HH];
__device__ __align__(16) unsigned short g_curh[BB*DD], g_curl[BB*DD];
__device__ unsigned int g_bar;

__device__ __forceinline__ uint32_t smem_u32(const void* p) {
    uint32_t a;
    asm("{ .reg .u64 t; cvta.to.shared.u64 t, %1; cvt.u32.u64 %0, t; }" : "=r"(a) : "l"(p));
    return a;
}
__device__ __forceinline__ void ldsm4(uint32_t r[4], uint32_t addr) {
    asm volatile("ldmatrix.sync.aligned.m8n8.x4.shared.b16 {%0,%1,%2,%3}, [%4];"
        : "=r"(r[0]), "=r"(r[1]), "=r"(r[2]), "=r"(r[3]) : "r"(addr));
}
__device__ __forceinline__ void mma_bf16(float c[4], const uint32_t a[4], uint32_t b0, uint32_t b1) {
    asm volatile("mma.sync.aligned.m16n8k16.row.col.f32.bf16.bf16.f32 "
        "{%0,%1,%2,%3}, {%4,%5,%6,%7}, {%8,%9}, {%0,%1,%2,%3};"
        : "+f"(c[0]), "+f"(c[1]), "+f"(c[2]), "+f"(c[3])
        : "r"(a[0]), "r"(a[1]), "r"(a[2]), "r"(a[3]), "r"(b0), "r"(b1));
}
__device__ __forceinline__ void bf16split(float v, unsigned short &hi, unsigned short &lo) {
    __nv_bfloat16 hb = __float2bfloat16(v);
    hi = __bfloat16_as_ushort(hb);
    lo = __bfloat16_as_ushort(__float2bfloat16(v - __bfloat162float(hb)));
}
// swizzled element index for h arrays (col in [0,512))
__device__ __forceinline__ int hswz(int r, int col) {
    int u = (col >> 3) & 7;
    return r*HH + (col >> 6)*64 + ((u ^ (r & 7)) << 3) + (col & 7);
}
// swizzled element index for cur (col in [0,64))
__device__ __forceinline__ int cswz(int r, int col) {
    return r*DD + (((col >> 3) ^ (r & 7)) << 3) + (col & 7);
}

__device__ __forceinline__ void grid_barrier() {
    __syncthreads();
    if (threadIdx.x == 0) {
        __threadfence();
        unsigned my = atomicAdd(&g_bar, 1u) + 1u;
        unsigned target = my + (NBLK - 1u) - ((my - 1u) % NBLK);
        while ((int)(*(volatile unsigned*)&g_bar - target) < 0) __nanosleep(32);
        __threadfence();
    }
    __syncthreads();
}

// copy one [128r x 64k] bf16 chunk (hi+lo) gmem -> smem tiles via cp.async (L2-only)
__device__ __forceinline__ void cpa_chunk(uint32_t smhi, uint32_t smlo,
        const unsigned short* __restrict__ ghi, const unsigned short* __restrict__ glo,
        int rowElems, int chunkElemOff, int stid) {
    #pragma unroll
    for (int q = 0; q < 4; q++) {
        int lin = q*256 + stid;
        int r = lin >> 3, cell = lin & 7;
        int gofs = r*rowElems + chunkElemOff + cell*8;
        uint32_t so = (uint32_t)(r*128 + cell*16);
        asm volatile("cp.async.cg.shared.global [%0], [%1], 16;"
            :: "r"(smhi + so), "l"(ghi + gofs) : "memory");
        asm volatile("cp.async.cg.shared.global [%0], [%1], 16;"
            :: "r"(smlo + so), "l"(glo + gofs) : "memory");
    }
    asm volatile("cp.async.commit_group;" ::: "memory");
}

// One 64-k chunk of MMAs, split accumulators (hi-term vs correction terms).
__device__ __forceinline__ void mma_chunk(float C0h[4], float C0l[4], float C1h[4], float C1l[4],
    uint32_t a_hi, uint32_t a_lo, int rsw, int ahalf, uint32_t bhi, uint32_t blo) {
    #pragma unroll
    for (int kk = 0; kk < 4; kk++) {
        uint32_t asw = (uint32_t)(((2*kk + ahalf) ^ rsw) << 4);
        uint32_t ah[4], al[4], bh[4], bl[4];
        ldsm4(ah, a_hi + asw);
        ldsm4(al, a_lo + asw);
        ldsm4(bh, bhi + kk*32);
        ldsm4(bl, blo + kk*32);
        mma_bf16(C0h, ah, bh[0], bh[1]);
        mma_bf16(C1h, ah, bh[2], bh[3]);
        mma_bf16(C0l, ah, bl[0], bl[1]);
        mma_bf16(C1l, ah, bl[2], bl[3]);
        mma_bf16(C0l, al, bh[0], bh[1]);
        mma_bf16(C1l, al, bh[2], bh[3]);
    }
}

__device__ __forceinline__ void gates2(const float C0[4], const float C1[4],
    float bi, float bf_, float bg, float bo, float cst[2], float hout[2]) {
    #pragma unroll
    for (int h = 0; h < 2; h++) {
        float zi = C0[2*h] + bi, zf = C0[2*h+1] + bf_;
        float zg = C1[2*h] + bg, zo = C1[2*h+1] + bo;
        float ig = 1.f/(1.f + expf(-zi));
        float fg = 1.f/(1.f + expf(-zf));
        float gg = tanhf(zg);
        float og = 1.f/(1.f + expf(-zo));
        float cn = fg*cst[h] + ig*gg;
        cst[h] = cn;
        hout[h] = og*tanhf(cn);
    }
}

__global__ void __launch_bounds__(NTHR, 1) ajrnn_kernel(
    const float* __restrict__ x,
    const float* __restrict__ k0, const float* __restrict__ r0, const float* __restrict__ b0,
    const float* __restrict__ k1, const float* __restrict__ r1, const float* __restrict__ b1,
    const float* __restrict__ Wm, const float* __restrict__ bias,
    float* __restrict__ out)
{
    extern __shared__ char smem[];
    const uint32_t smb = smem_u32(smem);
    const int tid = threadIdx.x;
    const int bid = blockIdx.x;
    const int n0  = bid * 4;
    const int dcol = bid >> 1;
    const int wid = tid >> 5, lane = tid & 31;
    float* sh_wp = (float*)(smem + SM_WP);

    // ---- weights: fp32 -> bf16 hi/lo, gate-interleaved col order ----
    unsigned short* w1h = (unsigned short*)(smem + SM_W1HI);
    unsigned short* w1l = (unsigned short*)(smem + SM_W1LO);
    unsigned short* w2h = (unsigned short*)(smem + SM_W2HI);
    unsigned short* w2l = (unsigned short*)(smem + SM_W2LO);
    for (int idx = tid; idx < 16*576; idx += NTHR) {
        int p = idx & 15, k = idx >> 4;
        int col = (2*(p>>3) + (p&1))*HH + n0 + ((p&7)>>1);
        float w = (k < DD) ? k0[k*2048 + col] : r0[(k-DD)*2048 + col];
        unsigned short hb, lb; bf16split(w, hb, lb);
        w1h[p*W1_STRIDE + k] = hb;
        w1l[p*W1_STRIDE + k] = lb;
    }
    for (int idx = tid; idx < 16*1024; idx += NTHR) {
        int p = idx & 15, k = idx >> 4;
        int col = (2*(p>>3) + (p&1))*HH + n0 + ((p&7)>>1);
        float w = (k < HH) ? k1[k*2048 + col] : r1[(k-HH)*2048 + col];
        unsigned short hb, lb; bf16split(w, hb, lb);
        w2h[p*W2_STRIDE + k] = hb;
        w2l[p*W2_STRIDE + k] = lb;
    }
    sh_wp[tid] = Wm[tid*DD + dcol];
    // zero global state (128 CTAs x 512 threads == BB*HH exactly)
    {
        int gidx = bid*NTHR + tid;
        g_h1h[0][gidx] = 0; g_h1l[0][gidx] = 0;
        g_h2h[0][gidx] = 0; g_h2l[0][gidx] = 0;
        g_h2f[0][gidx] = 0.f;
    }
    const float biasd = bias[dcol];

    const int jj = lane & 3;
    const float bi0 = b0[0*HH + n0 + jj], bf0 = b0[1*HH + n0 + jj];
    const float bg0 = b0[2*HH + n0 + jj], bo0 = b0[3*HH + n0 + jj];
    const float bi1 = b1[0*HH + n0 + jj], bf1 = b1[1*HH + n0 + jj];
    const float bg1 = b1[2*HH + n0 + jj], bo1 = b1[3*HH + n0 + jj];

    const int arow  = ((wid & 7) << 4) + (lane & 15);
    const int rsw   = arow & 7;
    const int ahalf = lane >> 4;
    const uint32_t a_row_off = (uint32_t)(arow * 128);
    const int bn  = (lane & 7) | ((lane >> 1) & 8);
    const int bk8 = (lane >> 3) & 1;
    const uint32_t b1h = smb + SM_W1HI + bn*(W1_STRIDE*2) + bk8*16;
    const uint32_t b1lo = smb + SM_W1LO + bn*(W1_STRIDE*2) + bk8*16;
    const uint32_t b2h = smb + SM_W2HI + bn*(W2_STRIDE*2) + bk8*16;
    const uint32_t b2lo = smb + SM_W2LO + bn*(W2_STRIDE*2) + bk8*16;
    const int crow = ((wid & 7) << 4) + (lane >> 2);
    const bool producer = (wid >= 8);
    const int stid = tid & 255;

    float c1st[2] = {0.f, 0.f}, c2st[2] = {0.f, 0.f};
    grid_barrier();

    // ---------------- time loop ----------------
    for (int t = 0; t < TT; t++) {
        const int rb = t & 1;
        const int wb = rb ^ 1;

        // ---- Phase A: pred (-> out) + imputed cur (writes bf16 hi/lo swizzled) ----
        {
            const int r  = ((bid & 1) * 64) + (tid >> 3);
            const int l8 = tid & 7;
            if (t == 0) {
                if (l8 == 0) {
                    float cv = x[(r*TT)*DD + dcol];
                    unsigned short chi, clo; bf16split(cv, chi, clo);
                    int ci = cswz(r, dcol);
                    g_curh[ci] = chi; g_curl[ci] = clo;
                }
            } else {
                const float* hrow = &g_h2f[rb][r*HH + l8*64];
                const float* wv = sh_wp + l8*64;
                float sacc = 0.f;
                #pragma unroll
                for (int kk = 0; kk < 64; kk += 4) {
                    float4 h4 = __ldcg((const float4*)(hrow + kk));
                    sacc += h4.x*wv[kk] + h4.y*wv[kk+1] + h4.z*wv[kk+2] + h4.w*wv[kk+3];
                }
                sacc += __shfl_xor_sync(0xffffffffu, sacc, 4);
                sacc += __shfl_xor_sync(0xffffffffu, sacc, 2);
                sacc += __shfl_xor_sync(0xffffffffu, sacc, 1);
                if (l8 == 0) {
                    float p  = sacc + biasd;
                    float xv = x[(r*TT + t)*DD + dcol];
                    float cv = (xv == 128.0f) ? p : xv;
                    unsigned short chi, clo; bf16split(cv, chi, clo);
                    int ci = cswz(r, dcol);
                    g_curh[ci] = chi; g_curl[ci] = clo;
                    out[(r*(TT-1) + (t-1))*DD + dcol] = p;
                }
            }
        }
        grid_barrier();

        // ---- Phase B: z = [cur | h1_old] @ W1, 9 chunks, cp.async pipeline ----
        {
            float C0h[4]={0,0,0,0}, C0l[4]={0,0,0,0}, C1h[4]={0,0,0,0}, C1l[4]={0,0,0,0};
            if (producer)
                cpa_chunk(smb + SM_A0HI, smb + SM_A0LO, g_curh, g_curl, DD, 0, stid);
            #pragma unroll 1
            for (int c = 0; c < 9; c++) {
                if (producer) {
                    if (c + 1 < 9) {
                        uint32_t bh = smb + (((c+1)&1) ? SM_A1HI : SM_A0HI);
                        uint32_t bl = smb + (((c+1)&1) ? SM_A1LO : SM_A0LO);
                        cpa_chunk(bh, bl, g_h1h[rb], g_h1l[rb], HH, c*64, stid);
                        asm volatile("cp.async.wait_group 1;" ::: "memory");
                    } else {
                        asm volatile("cp.async.wait_group 0;" ::: "memory");
                    }
                }
                __syncthreads();
                if (!producer) {
                    uint32_t ah = smb + ((c&1) ? SM_A1HI : SM_A0HI) + a_row_off;
                    uint32_t al = smb + ((c&1) ? SM_A1LO : SM_A0LO) + a_row_off;
                    mma_chunk(C0h, C0l, C1h, C1l, ah, al, rsw, ahalf, b1h + c*128, b1lo + c*128);
                }
                __syncthreads();
            }
            if (!producer) {
                float C0[4], C1[4];
                #pragma unroll
                for (int i = 0; i < 4; i++) { C0[i] = C0h[i] + C0l[i]; C1[i] = C1h[i] + C1l[i]; }
                float hout[2];
                gates2(C0, C1, bi0, bf0, bg0, bo0, c1st, hout);
                #pragma unroll
                for (int h = 0; h < 2; h++) {
                    int r = crow + 8*h;
                    unsigned short hi, lo; bf16split(hout[h], hi, lo);
                    int p = hswz(r, n0 + jj);
                    g_h1h[wb][p] = hi; g_h1l[wb][p] = lo;
                }
            }
        }
        grid_barrier();

        // ---- Phase C: z = [h1_new | h2_old] @ W2, 16 chunks, cp.async pipeline ----
        {
            float C0h[4]={0,0,0,0}, C0l[4]={0,0,0,0}, C1h[4]={0,0,0,0}, C1l[4]={0,0,0,0};
            if (producer)
                cpa_chunk(smb + SM_A0HI, smb + SM_A0LO, g_h1h[wb], g_h1l[wb], HH, 0, stid);
            #pragma unroll 1
            for (int c = 0; c < 16; c++) {
                if (producer) {
                    if (c + 1 < 16) {
                        int cc = c + 1;
                        const unsigned short* sh = (cc < 8) ? g_h1h[wb] : g_h2h[rb];
                        const unsigned short* sl = (cc < 8) ? g_h1l[wb] : g_h2l[rb];
                        int off = ((cc < 8) ? cc : (cc - 8)) * 64;
                        uint32_t bh = smb + ((cc&1) ? SM_A1HI : SM_A0HI);
                        uint32_t bl = smb + ((cc&1) ? SM_A1LO : SM_A0LO);
                        cpa_chunk(bh, bl, sh, sl, HH, off, stid);
                        asm volatile("cp.async.wait_group 1;" ::: "memory");
                    } else {
                        asm volatile("cp.async.wait_group 0;" ::: "memory");
                    }
                }
                __syncthreads();
                if (!producer) {
                    uint32_t ah = smb + ((c&1) ? SM_A1HI : SM_A0HI) + a_row_off;
                    uint32_t al = smb + ((c&1) ? SM_A1LO : SM_A0LO) + a_row_off;
                    mma_chunk(C0h, C0l, C1h, C1l, ah, al, rsw, ahalf, b2h + c*128, b2lo + c*128);
                }
                __syncthreads();
            }
            if (!producer) {
                float C0[4], C1[4];
                #pragma unroll
                for (int i = 0; i < 4; i++) { C0[i] = C0h[i] + C0l[i]; C1[i] = C1h[i] + C1l[i]; }
                float hout[2];
                gates2(C0, C1, bi1, bf1, bg1, bo1, c2st, hout);
                #pragma unroll
                for (int h = 0; h < 2; h++) {
                    int r = crow + 8*h;
                    unsigned short hi, lo; bf16split(hout[h], hi, lo);
                    int p = hswz(r, n0 + jj);
                    g_h2h[wb][p] = hi; g_h2l[wb][p] = lo;
                    g_h2f[wb][r*HH + n0 + jj] = hout[h];
                    if (t == TT-1) out[PRED_SZ + r*HH + n0 + jj] = hout[h];
                }
            }
        }
        grid_barrier();
    }
}

extern "C" void kernel_launch(void* const* d_in, const int* in_sizes, int n_in,
                              void* d_out, int out_size) {
    (void)in_sizes; (void)n_in; (void)out_size;
    const float* x    = (const float*)d_in[0];
    const float* k0   = (const float*)d_in[1];
    const float* r0   = (const float*)d_in[2];
    const float* b0   = (const float*)d_in[3];
    const float* k1   = (const float*)d_in[4];
    const float* r1   = (const float*)d_in[5];
    const float* b1   = (const float*)d_in[6];
    const float* Wm   = (const float*)d_in[7];
    const float* bias = (const float*)d_in[8];
    cudaFuncSetAttribute(ajrnn_kernel, cudaFuncAttributeMaxDynamicSharedMemorySize, SM_TOTAL);
    ajrnn_kernel<<<NBLK, NTHR, SM_TOTAL>>>(x, k0, r0, b0, k1, r1, b1, Wm, bias, (float*)d_out);
}